// round 1
// baseline (speedup 1.0000x reference)
#include <cuda_runtime.h>

#define D     128
#define NMAX  50000
#define EMAX  1600000

// ---------------- device scratch (allocation-free, static) ----------------
__device__ int       g_is64;
__device__ int       g_src[EMAX];
__device__ int       g_dst[EMAX];
__device__ float     g_scores[EMAX];
__device__ unsigned  g_m[NMAX];          // segment max, order-mapped uint
__device__ float     g_s[NMAX];          // segment sum of exp
__device__ float     g_Q[(size_t)NMAX * D];
__device__ float     g_K[(size_t)NMAX * D];
__device__ float     g_V[(size_t)NMAX * D];
__device__ float     g_H[(size_t)NMAX * D];   // layer-1 output / layer-2 input

// order-preserving float <-> uint map (for atomicMax on floats incl. negatives)
__device__ __forceinline__ unsigned ford(float f) {
    unsigned b = __float_as_uint(f);
    return (b & 0x80000000u) ? ~b : (b | 0x80000000u);
}
__device__ __forceinline__ float funord(unsigned u) {
    return (u & 0x80000000u) ? __uint_as_float(u ^ 0x80000000u)
                             : __uint_as_float(~u);
}
#define ORD_NEG_INF 0x007FFFFFu   // ford(-inf)

// ---------------- edge index width detection + conversion ----------------
// If edge_index is int64, the high 32-bit word of every value is 0
// (values in [0, 50000)). If int32, odd words are random node ids —
// probability all 64 are zero is ~(1/50000)^64.
__global__ void k_detect(const unsigned* __restrict__ ei) {
    if (threadIdx.x == 0) {
        int is64 = 1;
        for (int i = 0; i < 64; i++)
            if (ei[2 * i + 1] != 0u) is64 = 0;
        g_is64 = is64;
    }
}

__global__ void k_convert(const void* __restrict__ ei, int E) {
    int i = blockIdx.x * blockDim.x + threadIdx.x;
    if (i >= E) return;
    if (g_is64) {
        const long long* p = (const long long*)ei;
        g_src[i] = (int)p[i];
        g_dst[i] = (int)p[(size_t)E + i];
    } else {
        const int* p = (const int*)ei;
        g_src[i] = p[i];
        g_dst[i] = p[E + i];
    }
}

// ---------------- init: zero H, reset segment max/sum ----------------
__global__ void k_init(int N) {
    int i = blockIdx.x * blockDim.x + threadIdx.x;
    if (i < N * D) g_H[i] = 0.0f;
    if (i < N) { g_m[i] = ORD_NEG_INF; g_s[i] = 0.0f; }
}

// ---------------- fused QKV GEMM: C = X @ W^T + b ----------------
// Block tile 64x64, 256 threads, 4x4 per thread, K chunked by 32.
// blockIdx.y in [0,6): selects (Q|K|V) x (col half).
__global__ void k_gemm_qkv(const float* __restrict__ xin, int layer,
                           const float* __restrict__ qw, const float* __restrict__ qb,
                           const float* __restrict__ kw, const float* __restrict__ kb,
                           const float* __restrict__ vw, const float* __restrict__ vb,
                           int N) {
    const float* X = layer ? g_H : xin;
    __shared__ float As[32][68];
    __shared__ float Bs[32][68];

    int m0 = blockIdx.x * 64;
    int cb = blockIdx.y;
    int wsel = cb >> 1;
    const float* W = (wsel == 0) ? qw : (wsel == 1) ? kw : vw;
    const float* B = (wsel == 0) ? qb : (wsel == 1) ? kb : vb;
    float*       C = (wsel == 0) ? g_Q : (wsel == 1) ? g_K : g_V;
    int n0 = (cb & 1) * 64;

    int tid = threadIdx.x;
    int tx = tid & 15, ty = tid >> 4;

    float acc[4][4];
#pragma unroll
    for (int i = 0; i < 4; i++)
#pragma unroll
        for (int j = 0; j < 4; j++) acc[i][j] = 0.0f;

    for (int k0 = 0; k0 < D; k0 += 32) {
        // load X tile (64 rows x 32 cols) transposed into As[k][m]
#pragma unroll
        for (int f = tid; f < 512; f += 256) {
            int r = f >> 3, kq = (f & 7) * 4;
            int gr = m0 + r;
            float4 v = make_float4(0.f, 0.f, 0.f, 0.f);
            if (gr < N) v = *(const float4*)(X + (size_t)gr * D + k0 + kq);
            As[kq + 0][r] = v.x; As[kq + 1][r] = v.y;
            As[kq + 2][r] = v.z; As[kq + 3][r] = v.w;
        }
        // load W tile (rows n0..n0+63) transposed into Bs[k][n]
#pragma unroll
        for (int f = tid; f < 512; f += 256) {
            int r = f >> 3, kq = (f & 7) * 4;
            float4 v = *(const float4*)(W + (size_t)(n0 + r) * D + k0 + kq);
            Bs[kq + 0][r] = v.x; Bs[kq + 1][r] = v.y;
            Bs[kq + 2][r] = v.z; Bs[kq + 3][r] = v.w;
        }
        __syncthreads();
#pragma unroll
        for (int k = 0; k < 32; k++) {
            float4 a4 = *(const float4*)&As[k][ty * 4];
            float4 b4 = *(const float4*)&Bs[k][tx * 4];
            float av[4] = {a4.x, a4.y, a4.z, a4.w};
            float bv[4] = {b4.x, b4.y, b4.z, b4.w};
#pragma unroll
            for (int i = 0; i < 4; i++)
#pragma unroll
                for (int j = 0; j < 4; j++)
                    acc[i][j] += av[i] * bv[j];
        }
        __syncthreads();
    }

#pragma unroll
    for (int i = 0; i < 4; i++) {
        int gr = m0 + ty * 4 + i;
        if (gr >= N) continue;
#pragma unroll
        for (int j = 0; j < 4; j++) {
            int gc = n0 + tx * 4 + j;
            C[(size_t)gr * D + gc] = acc[i][j] + B[gc];
        }
    }
}

// ---------------- pass 1: per-edge score + segment max ----------------
// One warp per edge: coalesced 512B row reads of Q[dst], K[src].
__global__ void k_scores(int E) {
    int gid = blockIdx.x * blockDim.x + threadIdx.x;
    int w = gid >> 5;
    int lane = gid & 31;
    if (w >= E) return;
    int sN = g_src[w], dN = g_dst[w];
    float4 q = *((const float4*)(g_Q + (size_t)dN * D) + lane);
    float4 k = *((const float4*)(g_K + (size_t)sN * D) + lane);
    float p = q.x * k.x + q.y * k.y + q.z * k.z + q.w * k.w;
#pragma unroll
    for (int o = 16; o; o >>= 1) p += __shfl_xor_sync(0xFFFFFFFFu, p, o);
    if (lane == 0) {
        p *= 0.08838834764831845f;   // 1/sqrt(128)
        g_scores[w] = p;
        atomicMax(&g_m[dN], ford(p));
    }
}

// ---------------- pass 2: segment sum of exp(score - max) ----------------
__global__ void k_expsum(int E) {
    int i = blockIdx.x * blockDim.x + threadIdx.x;
    if (i >= E) return;
    int dN = g_dst[i];
    float ex = __expf(g_scores[i] - funord(g_m[dN]));
    atomicAdd(&g_s[dN], ex);
}

// ---------------- pass 3: weighted scatter-add of V[src] into out[dst] ---
__global__ void k_aggregate(float* __restrict__ dout, int layer, int E) {
    int gid = blockIdx.x * blockDim.x + threadIdx.x;
    int w = gid >> 5;
    int lane = gid & 31;
    if (w >= E) return;
    int sN = g_src[w], dN = g_dst[w];
    float a = 0.0f;
    if (lane == 0)
        a = __expf(g_scores[w] - funord(g_m[dN])) / g_s[dN];
    a = __shfl_sync(0xFFFFFFFFu, a, 0);
    float4 v = *((const float4*)(g_V + (size_t)sN * D) + lane);
    float* O = (layer ? dout : g_H) + (size_t)dN * D + lane * 4;
    asm volatile("red.global.add.v4.f32 [%0], {%1,%2,%3,%4};"
                 :: "l"(O), "f"(a * v.x), "f"(a * v.y), "f"(a * v.z), "f"(a * v.w)
                 : "memory");
}

// ---------------- between layers: ELU on H, zero d_out, reset m/s --------
__global__ void k_elu_reinit(float* __restrict__ dout, int N) {
    int i = blockIdx.x * blockDim.x + threadIdx.x;
    if (i < N * D) {
        float h = g_H[i];
        g_H[i] = (h > 0.0f) ? h : expm1f(h);
        dout[i] = 0.0f;
    }
    if (i < N) { g_m[i] = ORD_NEG_INF; g_s[i] = 0.0f; }
}

// ---------------- launch ----------------
extern "C" void kernel_launch(void* const* d_in, const int* in_sizes, int n_in,
                              void* d_out, int out_size) {
    const float* x   = (const float*)d_in[0];
    const void*  ei  = d_in[1];
    const float* q1w = (const float*)d_in[2];  const float* q1b = (const float*)d_in[3];
    const float* k1w = (const float*)d_in[4];  const float* k1b = (const float*)d_in[5];
    const float* v1w = (const float*)d_in[6];  const float* v1b = (const float*)d_in[7];
    const float* q2w = (const float*)d_in[8];  const float* q2b = (const float*)d_in[9];
    const float* k2w = (const float*)d_in[10]; const float* k2b = (const float*)d_in[11];
    const float* v2w = (const float*)d_in[12]; const float* v2b = (const float*)d_in[13];

    int N = in_sizes[0] / D;
    int E = in_sizes[1] / 2;
    float* out = (float*)d_out;

    k_detect<<<1, 32>>>((const unsigned*)ei);
    k_convert<<<(E + 255) / 256, 256>>>(ei, E);
    k_init<<<(N * D + 255) / 256, 256>>>(N);

    dim3 ggrid((N + 63) / 64, 6);
    int eb_warp = (E * 32 + 255) / 256;   // warp-per-edge grids
    int eb_thr  = (E + 255) / 256;

    // ---- layer 1 ----
    k_gemm_qkv<<<ggrid, 256>>>(x, 0, q1w, q1b, k1w, k1b, v1w, v1b, N);
    k_scores<<<eb_warp, 256>>>(E);
    k_expsum<<<eb_thr, 256>>>(E);
    k_aggregate<<<eb_warp, 256>>>(out, 0, E);

    // ---- ELU + reset ----
    k_elu_reinit<<<(N * D + 255) / 256, 256>>>(out, N);

    // ---- layer 2 ----
    k_gemm_qkv<<<ggrid, 256>>>(x, 1, q2w, q2b, k2w, k2b, v2w, v2b, N);
    k_scores<<<eb_warp, 256>>>(E);
    k_expsum<<<eb_thr, 256>>>(E);
    k_aggregate<<<eb_warp, 256>>>(out, 1, E);
}

// round 3
// speedup vs baseline: 2.1862x; 2.1862x over previous
#include <cuda_runtime.h>
#include <math_constants.h>

#define D     128
#define NMAX  50000
#define EMAX  1600000

// ---------------- device scratch (allocation-free, static) ----------------
__device__ int g_is64;
__device__ int g_src[EMAX];
__device__ int g_dst[EMAX];
__device__ int g_deg[NMAX];
__device__ int g_start[NMAX + 1];
__device__ int g_cursor[NMAX];
__device__ int g_csr_src[EMAX];

__device__ __align__(256) float g_Q[(size_t)NMAX * D];        // [N,128]
__device__ __align__(256) float g_KV[(size_t)NMAX * 2 * D];   // [N,256]: K | V interleaved
__device__ __align__(256) float g_H[(size_t)NMAX * D];        // layer-1 output

// ---------------- edge index width detection ----------------
// int64 values in [0,50000) have zero high words; int32 data would make the
// odd 32-bit words random node ids (P[all 64 zero] ~ (1/50000)^64).
__global__ void k_detect(const unsigned* __restrict__ ei) {
    if (threadIdx.x == 0) {
        int is64 = 1;
        for (int i = 0; i < 64; i++)
            if (ei[2 * i + 1] != 0u) is64 = 0;
        g_is64 = is64;
    }
}

__global__ void k_zero_deg(int N) {
    int i = blockIdx.x * blockDim.x + threadIdx.x;
    if (i < N) g_deg[i] = 0;
}

// convert edge_index to int32 src/dst and build dst-degree histogram
__global__ void k_convert(const void* __restrict__ ei, int E) {
    int i = blockIdx.x * blockDim.x + threadIdx.x;
    if (i >= E) return;
    int s, d;
    if (g_is64) {
        const long long* p = (const long long*)ei;
        s = (int)p[i];
        d = (int)p[(size_t)E + i];
    } else {
        const int* p = (const int*)ei;
        s = p[i];
        d = p[E + i];
    }
    g_src[i] = s;
    g_dst[i] = d;
    atomicAdd(&g_deg[d], 1);
}

// single-block exclusive scan over g_deg -> g_start (and g_cursor copy)
__global__ void k_scan(int N) {
    __shared__ int sh[1024];
    __shared__ int s_carry;
    int tid = threadIdx.x;
    if (tid == 0) s_carry = 0;
    __syncthreads();
    for (int base = 0; base < N; base += 1024) {
        int idx = base + tid;
        int v = (idx < N) ? g_deg[idx] : 0;
        sh[tid] = v;
        __syncthreads();
        for (int off = 1; off < 1024; off <<= 1) {
            int t = (tid >= off) ? sh[tid - off] : 0;
            __syncthreads();
            sh[tid] += t;
            __syncthreads();
        }
        if (idx < N) {
            int excl = s_carry + sh[tid] - v;
            g_start[idx] = excl;
            g_cursor[idx] = excl;
        }
        int tot = sh[1023];
        __syncthreads();
        if (tid == 0) s_carry += tot;
        __syncthreads();
    }
    if (tid == 0) g_start[N] = s_carry;
}

__global__ void k_scatter(int E) {
    int i = blockIdx.x * blockDim.x + threadIdx.x;
    if (i >= E) return;
    int d = g_dst[i];
    int pos = atomicAdd(&g_cursor[d], 1);
    g_csr_src[pos] = g_src[i];
}

// ---------------- fused QKV GEMM: C = X @ W^T + b ----------------
// 128x128 CTA tile, 256 threads, 8x8 per thread in split blocks:
// rows {ty*4..+3, 64+ty*4..+3}, cols {tx*4..+3, 64+tx*4..+3}.
// blockIdx.y selects Q / K / V (K,V written interleaved into g_KV).
__global__ void __launch_bounds__(256, 2)
k_gemm_qkv(const float* __restrict__ xin, int layer,
           const float* __restrict__ qw, const float* __restrict__ qb,
           const float* __restrict__ kw, const float* __restrict__ kb,
           const float* __restrict__ vw, const float* __restrict__ vb,
           int N) {
    const float* X = layer ? g_H : xin;
    __shared__ float As[16][132];
    __shared__ float Bs[16][132];

    int wsel = blockIdx.y;
    const float* W = (wsel == 0) ? qw : (wsel == 1) ? kw : vw;
    const float* Bb = (wsel == 0) ? qb : (wsel == 1) ? kb : vb;
    float* C;
    int cs;
    if (wsel == 0)      { C = g_Q;        cs = 128; }
    else if (wsel == 1) { C = g_KV;       cs = 256; }
    else                { C = g_KV + 128; cs = 256; }

    int m0 = blockIdx.x * 128;
    int tid = threadIdx.x;
    int tx = tid & 15, ty = tid >> 4;

    float acc[8][8];
#pragma unroll
    for (int i = 0; i < 8; i++)
#pragma unroll
        for (int j = 0; j < 8; j++) acc[i][j] = 0.0f;

    for (int k0 = 0; k0 < D; k0 += 16) {
        // X tile: 128 rows x 16 k, transposed into As[k][m]
#pragma unroll
        for (int f = tid; f < 512; f += 256) {
            int r = f >> 2, kq = (f & 3) * 4;
            int gr = m0 + r;
            float4 v = make_float4(0.f, 0.f, 0.f, 0.f);
            if (gr < N) v = *(const float4*)(X + (size_t)gr * D + k0 + kq);
            As[kq + 0][r] = v.x; As[kq + 1][r] = v.y;
            As[kq + 2][r] = v.z; As[kq + 3][r] = v.w;
        }
        // W tile: 128 rows x 16 k, transposed into Bs[k][n]
#pragma unroll
        for (int f = tid; f < 512; f += 256) {
            int r = f >> 2, kq = (f & 3) * 4;
            float4 v = *(const float4*)(W + (size_t)r * D + k0 + kq);
            Bs[kq + 0][r] = v.x; Bs[kq + 1][r] = v.y;
            Bs[kq + 2][r] = v.z; Bs[kq + 3][r] = v.w;
        }
        __syncthreads();
#pragma unroll
        for (int k = 0; k < 16; k++) {
            float4 a0 = *(const float4*)&As[k][ty * 4];
            float4 a1 = *(const float4*)&As[k][64 + ty * 4];
            float4 b0 = *(const float4*)&Bs[k][tx * 4];
            float4 b1 = *(const float4*)&Bs[k][64 + tx * 4];
            float a[8] = {a0.x, a0.y, a0.z, a0.w, a1.x, a1.y, a1.z, a1.w};
            float b[8] = {b0.x, b0.y, b0.z, b0.w, b1.x, b1.y, b1.z, b1.w};
#pragma unroll
            for (int i = 0; i < 8; i++)
#pragma unroll
                for (int j = 0; j < 8; j++)
                    acc[i][j] += a[i] * b[j];
        }
        __syncthreads();
    }

#pragma unroll
    for (int gi = 0; gi < 2; gi++) {
#pragma unroll
        for (int i = 0; i < 4; i++) {
            int gr = m0 + gi * 64 + ty * 4 + i;
            if (gr >= N) continue;
            int ai = gi * 4 + i;
#pragma unroll
            for (int gj = 0; gj < 2; gj++) {
                int gc = gj * 64 + tx * 4;
                int aj = gj * 4;
                float4 o;
                o.x = acc[ai][aj + 0] + Bb[gc + 0];
                o.y = acc[ai][aj + 1] + Bb[gc + 1];
                o.z = acc[ai][aj + 2] + Bb[gc + 2];
                o.w = acc[ai][aj + 3] + Bb[gc + 3];
                *(float4*)(C + (size_t)gr * cs + gc) = o;
            }
        }
    }
}

// ---------------- fused attention: warp per dst node, online softmax ------
// layer==0: write g_H (device symbol, selected IN DEVICE CODE) with ELU.
// layer==1: write dout.
__global__ void k_attn(float* __restrict__ dout, int layer, int N) {
    int gw = (blockIdx.x * blockDim.x + threadIdx.x) >> 5;
    int lane = threadIdx.x & 31;
    if (gw >= N) return;

    float* outp = layer ? dout : g_H;   // device-side symbol selection (R2 bugfix)

    int beg = g_start[gw], end = g_start[gw + 1];
    float4 q = ((const float4*)(g_Q + (size_t)gw * D))[lane];

    float m = -CUDART_INF_F, s = 0.0f;
    float4 acc = make_float4(0.f, 0.f, 0.f, 0.f);

    float4 kf, vf;
    if (beg < end) {
        int sp = g_csr_src[beg];
        const float4* kv = (const float4*)(g_KV + (size_t)sp * 256);
        kf = kv[lane];
        vf = kv[32 + lane];
    }

    for (int e = beg; e < end; e++) {
        float4 kc = kf, vc = vf;
        if (e + 1 < end) {                      // prefetch next edge (MLP=2)
            int sp = g_csr_src[e + 1];
            const float4* kv = (const float4*)(g_KV + (size_t)sp * 256);
            kf = kv[lane];
            vf = kv[32 + lane];
        }
        float p = kc.x * q.x + kc.y * q.y + kc.z * q.z + kc.w * q.w;
#pragma unroll
        for (int o = 16; o; o >>= 1) p += __shfl_xor_sync(0xFFFFFFFFu, p, o);
        p *= 0.08838834764831845f;              // 1/sqrt(128)

        float mn = fmaxf(m, p);
        float c  = __expf(m - mn);              // exp(-inf)=0 on first edge
        float ep = __expf(p - mn);
        s = s * c + ep;
        acc.x = acc.x * c + ep * vc.x;
        acc.y = acc.y * c + ep * vc.y;
        acc.z = acc.z * c + ep * vc.z;
        acc.w = acc.w * c + ep * vc.w;
        m = mn;
    }

    float inv = (s > 0.0f) ? 1.0f / s : 0.0f;   // deg==0 -> zeros (matches ref)
    float4 o = make_float4(acc.x * inv, acc.y * inv, acc.z * inv, acc.w * inv);
    if (!layer) {                                // ELU fused into layer-1 epilogue
        o.x = (o.x > 0.f) ? o.x : expm1f(o.x);
        o.y = (o.y > 0.f) ? o.y : expm1f(o.y);
        o.z = (o.z > 0.f) ? o.z : expm1f(o.z);
        o.w = (o.w > 0.f) ? o.w : expm1f(o.w);
    }
    ((float4*)(outp + (size_t)gw * D))[lane] = o;
}

// ---------------- launch ----------------
extern "C" void kernel_launch(void* const* d_in, const int* in_sizes, int n_in,
                              void* d_out, int out_size) {
    const float* x   = (const float*)d_in[0];
    const void*  ei  = d_in[1];
    const float* q1w = (const float*)d_in[2];  const float* q1b = (const float*)d_in[3];
    const float* k1w = (const float*)d_in[4];  const float* k1b = (const float*)d_in[5];
    const float* v1w = (const float*)d_in[6];  const float* v1b = (const float*)d_in[7];
    const float* q2w = (const float*)d_in[8];  const float* q2b = (const float*)d_in[9];
    const float* k2w = (const float*)d_in[10]; const float* k2b = (const float*)d_in[11];
    const float* v2w = (const float*)d_in[12]; const float* v2b = (const float*)d_in[13];

    int N = in_sizes[0] / D;
    int E = in_sizes[1] / 2;
    float* out = (float*)d_out;

    int eb = (E + 255) / 256;
    int nb = (N + 255) / 256;

    // CSR build (shared by both layers)
    k_detect<<<1, 32>>>((const unsigned*)ei);
    k_zero_deg<<<nb, 256>>>(N);
    k_convert<<<eb, 256>>>(ei, E);
    k_scan<<<1, 1024>>>(N);
    k_scatter<<<eb, 256>>>(E);

    dim3 ggrid((N + 127) / 128, 3);
    int ab = (N * 32 + 255) / 256;

    // layer 1 (k_attn writes g_H internally, ELU fused)
    k_gemm_qkv<<<ggrid, 256>>>(x, 0, q1w, q1b, k1w, k1b, v1w, v1b, N);
    k_attn<<<ab, 256>>>(out, 0, N);

    // layer 2
    k_gemm_qkv<<<ggrid, 256>>>(x, 1, q2w, q2b, k2w, k2b, v2w, v2b, N);
    k_attn<<<ab, 256>>>(out, 1, N);
}

// round 4
// speedup vs baseline: 2.4227x; 1.1081x over previous
#include <cuda_runtime.h>
#include <math_constants.h>

#define D     128
#define NMAX  50000
#define EMAX  1600000

// ---------------- device scratch (allocation-free, static) ----------------
__device__ int g_is64;
__device__ int g_src[EMAX];
__device__ int g_dst[EMAX];
__device__ __align__(16) int g_deg[NMAX + 4];
__device__ __align__(16) int g_start[NMAX + 4];
__device__ __align__(16) int g_cursor[NMAX + 4];
__device__ int g_csr_src[EMAX];

__device__ __align__(256) float g_Q[(size_t)NMAX * D];        // [N,128]
__device__ __align__(256) float g_KV[(size_t)NMAX * 2 * D];   // [N,256]: K | V interleaved
__device__ __align__(256) float g_H[(size_t)NMAX * D];        // layer-1 output

// ---------------- edge index width detection ----------------
// int64 values in [0,50000) have zero high words; int32 data would make the
// odd 32-bit words random node ids (P[all 64 zero] ~ (1/50000)^64).
__global__ void k_detect(const unsigned* __restrict__ ei) {
    if (threadIdx.x == 0) {
        int is64 = 1;
        for (int i = 0; i < 64; i++)
            if (ei[2 * i + 1] != 0u) is64 = 0;
        g_is64 = is64;
    }
}

__global__ void k_zero_deg(int N) {
    int i = blockIdx.x * blockDim.x + threadIdx.x;
    if (i < N) g_deg[i] = 0;
}

// convert edge_index to int32 src/dst and build dst-degree histogram
__global__ void k_convert(const void* __restrict__ ei, int E) {
    int i = blockIdx.x * blockDim.x + threadIdx.x;
    if (i >= E) return;
    int s, d;
    if (g_is64) {
        const long long* p = (const long long*)ei;
        s = (int)p[i];
        d = (int)p[(size_t)E + i];
    } else {
        const int* p = (const int*)ei;
        s = p[i];
        d = p[E + i];
    }
    g_src[i] = s;
    g_dst[i] = d;
    atomicAdd(&g_deg[d], 1);
}

// ---------------- fast single-block exclusive scan (R3 fix) ----------------
// 1024 threads, 4 items/thread per tile (int4), warp-shuffle scans.
// ~52 barriers total vs ~1000 in the old Hillis-Steele version.
__global__ void k_scan(int N) {
    __shared__ int warp_sums[32];
    __shared__ int s_carry;
    int tid = threadIdx.x, lane = tid & 31, wid = tid >> 5;
    if (tid == 0) s_carry = 0;
    __syncthreads();

    const int TILE = 4096;  // 1024 threads * 4 items
    for (int base = 0; base < N; base += TILE) {
        int idx = base + tid * 4;
        int4 v = make_int4(0, 0, 0, 0);
        if (idx + 3 < N) v = *(const int4*)&g_deg[idx];
        else {
            if (idx + 0 < N) v.x = g_deg[idx + 0];
            if (idx + 1 < N) v.y = g_deg[idx + 1];
            if (idx + 2 < N) v.z = g_deg[idx + 2];
            if (idx + 3 < N) v.w = g_deg[idx + 3];
        }
        // thread-local inclusive
        int t0 = v.x, t1 = t0 + v.y, t2 = t1 + v.z, t3 = t2 + v.w;
        // warp inclusive scan of thread totals
        int inc = t3;
#pragma unroll
        for (int o = 1; o < 32; o <<= 1) {
            int n = __shfl_up_sync(0xFFFFFFFFu, inc, o);
            if (lane >= o) inc += n;
        }
        if (lane == 31) warp_sums[wid] = inc;
        __syncthreads();
        if (wid == 0) {
            int ws = warp_sums[lane];
#pragma unroll
            for (int o = 1; o < 32; o <<= 1) {
                int n = __shfl_up_sync(0xFFFFFFFFu, ws, o);
                if (lane >= o) ws += n;
            }
            warp_sums[lane] = ws;
        }
        __syncthreads();
        int warp_off = wid ? warp_sums[wid - 1] : 0;
        int e0 = s_carry + warp_off + (inc - t3);   // exclusive prefix of item 0
        int tile_total = warp_sums[31];

        if (idx + 3 < N) {
            int4 e = make_int4(e0, e0 + t0, e0 + t1, e0 + t2);
            *(int4*)&g_start[idx]  = e;
            *(int4*)&g_cursor[idx] = e;
        } else {
            if (idx + 0 < N) { g_start[idx + 0] = e0;      g_cursor[idx + 0] = e0;      }
            if (idx + 1 < N) { g_start[idx + 1] = e0 + t0; g_cursor[idx + 1] = e0 + t0; }
            if (idx + 2 < N) { g_start[idx + 2] = e0 + t1; g_cursor[idx + 2] = e0 + t1; }
            if (idx + 3 < N) { g_start[idx + 3] = e0 + t2; g_cursor[idx + 3] = e0 + t2; }
        }
        __syncthreads();                 // all reads of s_carry done
        if (tid == 0) s_carry += tile_total;
        __syncthreads();
    }
    if (tid == 0) g_start[N] = s_carry;
}

__global__ void k_scatter(int E) {
    int i = blockIdx.x * blockDim.x + threadIdx.x;
    if (i >= E) return;
    int d = g_dst[i];
    int pos = atomicAdd(&g_cursor[d], 1);
    g_csr_src[pos] = g_src[i];
}

// ---------------- fused QKV GEMM: C = X @ W^T + b ----------------
// 128x128 CTA tile, 256 threads, 8x8 per thread in split blocks.
// blockIdx.y selects Q / K / V (K,V written interleaved into g_KV).
__global__ void __launch_bounds__(256, 2)
k_gemm_qkv(const float* __restrict__ xin, int layer,
           const float* __restrict__ qw, const float* __restrict__ qb,
           const float* __restrict__ kw, const float* __restrict__ kb,
           const float* __restrict__ vw, const float* __restrict__ vb,
           int N) {
    const float* X = layer ? g_H : xin;
    __shared__ float As[16][132];
    __shared__ float Bs[16][132];

    int wsel = blockIdx.y;
    const float* W = (wsel == 0) ? qw : (wsel == 1) ? kw : vw;
    const float* Bb = (wsel == 0) ? qb : (wsel == 1) ? kb : vb;
    float* C;
    int cs;
    if (wsel == 0)      { C = g_Q;        cs = 128; }
    else if (wsel == 1) { C = g_KV;       cs = 256; }
    else                { C = g_KV + 128; cs = 256; }

    int m0 = blockIdx.x * 128;
    int tid = threadIdx.x;
    int tx = tid & 15, ty = tid >> 4;

    float acc[8][8];
#pragma unroll
    for (int i = 0; i < 8; i++)
#pragma unroll
        for (int j = 0; j < 8; j++) acc[i][j] = 0.0f;

    for (int k0 = 0; k0 < D; k0 += 16) {
#pragma unroll
        for (int f = tid; f < 512; f += 256) {
            int r = f >> 2, kq = (f & 3) * 4;
            int gr = m0 + r;
            float4 v = make_float4(0.f, 0.f, 0.f, 0.f);
            if (gr < N) v = *(const float4*)(X + (size_t)gr * D + k0 + kq);
            As[kq + 0][r] = v.x; As[kq + 1][r] = v.y;
            As[kq + 2][r] = v.z; As[kq + 3][r] = v.w;
        }
#pragma unroll
        for (int f = tid; f < 512; f += 256) {
            int r = f >> 2, kq = (f & 3) * 4;
            float4 v = *(const float4*)(W + (size_t)r * D + k0 + kq);
            Bs[kq + 0][r] = v.x; Bs[kq + 1][r] = v.y;
            Bs[kq + 2][r] = v.z; Bs[kq + 3][r] = v.w;
        }
        __syncthreads();
#pragma unroll
        for (int k = 0; k < 16; k++) {
            float4 a0 = *(const float4*)&As[k][ty * 4];
            float4 a1 = *(const float4*)&As[k][64 + ty * 4];
            float4 b0 = *(const float4*)&Bs[k][tx * 4];
            float4 b1 = *(const float4*)&Bs[k][64 + tx * 4];
            float a[8] = {a0.x, a0.y, a0.z, a0.w, a1.x, a1.y, a1.z, a1.w};
            float b[8] = {b0.x, b0.y, b0.z, b0.w, b1.x, b1.y, b1.z, b1.w};
#pragma unroll
            for (int i = 0; i < 8; i++)
#pragma unroll
                for (int j = 0; j < 8; j++)
                    acc[i][j] += a[i] * b[j];
        }
        __syncthreads();
    }

#pragma unroll
    for (int gi = 0; gi < 2; gi++) {
#pragma unroll
        for (int i = 0; i < 4; i++) {
            int gr = m0 + gi * 64 + ty * 4 + i;
            if (gr >= N) continue;
            int ai = gi * 4 + i;
#pragma unroll
            for (int gj = 0; gj < 2; gj++) {
                int gc = gj * 64 + tx * 4;
                int aj = gj * 4;
                float4 o;
                o.x = acc[ai][aj + 0] + Bb[gc + 0];
                o.y = acc[ai][aj + 1] + Bb[gc + 1];
                o.z = acc[ai][aj + 2] + Bb[gc + 2];
                o.w = acc[ai][aj + 3] + Bb[gc + 3];
                *(float4*)(C + (size_t)gr * cs + gc) = o;
            }
        }
    }
}

// ---------------- fused attention: warp per dst node, online softmax ------
// layer==0: write g_H (selected in device code) with ELU; layer==1: write dout.
__global__ void k_attn(float* __restrict__ dout, int layer, int N) {
    int gw = (blockIdx.x * blockDim.x + threadIdx.x) >> 5;
    int lane = threadIdx.x & 31;
    if (gw >= N) return;

    float* outp = layer ? dout : g_H;

    int beg = g_start[gw], end = g_start[gw + 1];
    float4 q = ((const float4*)(g_Q + (size_t)gw * D))[lane];

    float m = -CUDART_INF_F, s = 0.0f;
    float4 acc = make_float4(0.f, 0.f, 0.f, 0.f);

    float4 kf, vf;
    if (beg < end) {
        int sp = g_csr_src[beg];
        const float4* kv = (const float4*)(g_KV + (size_t)sp * 256);
        kf = kv[lane];
        vf = kv[32 + lane];
    }

    for (int e = beg; e < end; e++) {
        float4 kc = kf, vc = vf;
        if (e + 1 < end) {                      // prefetch next edge
            int sp = g_csr_src[e + 1];
            const float4* kv = (const float4*)(g_KV + (size_t)sp * 256);
            kf = kv[lane];
            vf = kv[32 + lane];
        }
        float p = kc.x * q.x + kc.y * q.y + kc.z * q.z + kc.w * q.w;
#pragma unroll
        for (int o = 16; o; o >>= 1) p += __shfl_xor_sync(0xFFFFFFFFu, p, o);
        p *= 0.08838834764831845f;              // 1/sqrt(128)

        float mn = fmaxf(m, p);
        float c  = __expf(m - mn);              // exp(-inf)=0 on first edge
        float ep = __expf(p - mn);
        s = s * c + ep;
        acc.x = acc.x * c + ep * vc.x;
        acc.y = acc.y * c + ep * vc.y;
        acc.z = acc.z * c + ep * vc.z;
        acc.w = acc.w * c + ep * vc.w;
        m = mn;
    }

    float inv = (s > 0.0f) ? 1.0f / s : 0.0f;   // deg==0 -> zeros (matches ref)
    float4 o = make_float4(acc.x * inv, acc.y * inv, acc.z * inv, acc.w * inv);
    if (!layer) {                                // ELU fused into layer-1 epilogue
        o.x = (o.x > 0.f) ? o.x : expm1f(o.x);
        o.y = (o.y > 0.f) ? o.y : expm1f(o.y);
        o.z = (o.z > 0.f) ? o.z : expm1f(o.z);
        o.w = (o.w > 0.f) ? o.w : expm1f(o.w);
    }
    ((float4*)(outp + (size_t)gw * D))[lane] = o;
}

// ---------------- launch ----------------
extern "C" void kernel_launch(void* const* d_in, const int* in_sizes, int n_in,
                              void* d_out, int out_size) {
    const float* x   = (const float*)d_in[0];
    const void*  ei  = d_in[1];
    const float* q1w = (const float*)d_in[2];  const float* q1b = (const float*)d_in[3];
    const float* k1w = (const float*)d_in[4];  const float* k1b = (const float*)d_in[5];
    const float* v1w = (const float*)d_in[6];  const float* v1b = (const float*)d_in[7];
    const float* q2w = (const float*)d_in[8];  const float* q2b = (const float*)d_in[9];
    const float* k2w = (const float*)d_in[10]; const float* k2b = (const float*)d_in[11];
    const float* v2w = (const float*)d_in[12]; const float* v2b = (const float*)d_in[13];

    int N = in_sizes[0] / D;
    int E = in_sizes[1] / 2;
    float* out = (float*)d_out;

    int eb = (E + 255) / 256;
    int nb = (N + 255) / 256;

    // CSR build (shared by both layers)
    k_detect<<<1, 32>>>((const unsigned*)ei);
    k_zero_deg<<<nb, 256>>>(N);
    k_convert<<<eb, 256>>>(ei, E);
    k_scan<<<1, 1024>>>(N);
    k_scatter<<<eb, 256>>>(E);

    dim3 ggrid((N + 127) / 128, 3);
    int ab = (N * 32 + 255) / 256;

    // layer 1 (k_attn writes g_H internally, ELU fused)
    k_gemm_qkv<<<ggrid, 256>>>(x, 0, q1w, q1b, k1w, k1b, v1w, v1b, N);
    k_attn<<<ab, 256>>>(out, 0, N);

    // layer 2
    k_gemm_qkv<<<ggrid, 256>>>(x, 1, q2w, q2b, k2w, k2b, v2w, v2b, N);
    k_attn<<<ab, 256>>>(out, 1, N);
}

// round 5
// speedup vs baseline: 2.4929x; 1.0290x over previous
#include <cuda_runtime.h>
#include <math_constants.h>

#define D     128
#define NMAX  50000
#define EMAX  1600000

// ---------------- device scratch (allocation-free, static) ----------------
__device__ int g_is64;
__device__ int g_src[EMAX];
__device__ int g_dst[EMAX];
__device__ __align__(16) int g_deg[NMAX + 4];
__device__ __align__(16) int g_start[NMAX + 4];
__device__ __align__(16) int g_cursor[NMAX + 4];
__device__ int g_csr_src[EMAX];

__device__ __align__(256) float g_Q[(size_t)NMAX * D];        // [N,128]
__device__ __align__(256) float g_KV[(size_t)NMAX * 2 * D];   // [N,256]: K | V interleaved
__device__ __align__(256) float g_H[(size_t)NMAX * D];        // layer-1 output

// ---------------- zero degree histogram + edge width detection (fused) ----
// int64 values in [0,50000) have zero high words; int32 data would make the
// odd 32-bit words random node ids (P[all 64 zero] ~ (1/50000)^64).
__global__ void k_init_csr(const unsigned* __restrict__ ei, int N) {
    int i = blockIdx.x * blockDim.x + threadIdx.x;
    if (i < N) g_deg[i] = 0;
    if (i == 0) {
        int is64 = 1;
        for (int j = 0; j < 64; j++)
            if (ei[2 * j + 1] != 0u) is64 = 0;
        g_is64 = is64;
    }
}

// convert edge_index to int32 src/dst and build dst-degree histogram
__global__ void k_convert(const void* __restrict__ ei, int E) {
    int i = blockIdx.x * blockDim.x + threadIdx.x;
    if (i >= E) return;
    int s, d;
    if (g_is64) {
        const long long* p = (const long long*)ei;
        s = (int)p[i];
        d = (int)p[(size_t)E + i];
    } else {
        const int* p = (const int*)ei;
        s = p[i];
        d = p[E + i];
    }
    g_src[i] = s;
    g_dst[i] = d;
    atomicAdd(&g_deg[d], 1);
}

// ---------------- fast single-block exclusive scan ----------------
__global__ void k_scan(int N) {
    __shared__ int warp_sums[32];
    __shared__ int s_carry;
    int tid = threadIdx.x, lane = tid & 31, wid = tid >> 5;
    if (tid == 0) s_carry = 0;
    __syncthreads();

    const int TILE = 4096;  // 1024 threads * 4 items
    for (int base = 0; base < N; base += TILE) {
        int idx = base + tid * 4;
        int4 v = make_int4(0, 0, 0, 0);
        if (idx + 3 < N) v = *(const int4*)&g_deg[idx];
        else {
            if (idx + 0 < N) v.x = g_deg[idx + 0];
            if (idx + 1 < N) v.y = g_deg[idx + 1];
            if (idx + 2 < N) v.z = g_deg[idx + 2];
            if (idx + 3 < N) v.w = g_deg[idx + 3];
        }
        int t0 = v.x, t1 = t0 + v.y, t2 = t1 + v.z, t3 = t2 + v.w;
        int inc = t3;
#pragma unroll
        for (int o = 1; o < 32; o <<= 1) {
            int n = __shfl_up_sync(0xFFFFFFFFu, inc, o);
            if (lane >= o) inc += n;
        }
        if (lane == 31) warp_sums[wid] = inc;
        __syncthreads();
        if (wid == 0) {
            int ws = warp_sums[lane];
#pragma unroll
            for (int o = 1; o < 32; o <<= 1) {
                int n = __shfl_up_sync(0xFFFFFFFFu, ws, o);
                if (lane >= o) ws += n;
            }
            warp_sums[lane] = ws;
        }
        __syncthreads();
        int warp_off = wid ? warp_sums[wid - 1] : 0;
        int e0 = s_carry + warp_off + (inc - t3);
        int tile_total = warp_sums[31];

        if (idx + 3 < N) {
            int4 e = make_int4(e0, e0 + t0, e0 + t1, e0 + t2);
            *(int4*)&g_start[idx]  = e;
            *(int4*)&g_cursor[idx] = e;
        } else {
            if (idx + 0 < N) { g_start[idx + 0] = e0;      g_cursor[idx + 0] = e0;      }
            if (idx + 1 < N) { g_start[idx + 1] = e0 + t0; g_cursor[idx + 1] = e0 + t0; }
            if (idx + 2 < N) { g_start[idx + 2] = e0 + t1; g_cursor[idx + 2] = e0 + t1; }
            if (idx + 3 < N) { g_start[idx + 3] = e0 + t2; g_cursor[idx + 3] = e0 + t2; }
        }
        __syncthreads();
        if (tid == 0) s_carry += tile_total;
        __syncthreads();
    }
    if (tid == 0) g_start[N] = s_carry;
}

__global__ void k_scatter(int E) {
    int i = blockIdx.x * blockDim.x + threadIdx.x;
    if (i >= E) return;
    int d = g_dst[i];
    int pos = atomicAdd(&g_cursor[d], 1);
    g_csr_src[pos] = g_src[i];
}

// ---------------- fused QKV GEMM: C = X @ W^T + b ----------------
__global__ void __launch_bounds__(256, 2)
k_gemm_qkv(const float* __restrict__ xin, int layer,
           const float* __restrict__ qw, const float* __restrict__ qb,
           const float* __restrict__ kw, const float* __restrict__ kb,
           const float* __restrict__ vw, const float* __restrict__ vb,
           int N) {
    const float* X = layer ? g_H : xin;
    __shared__ float As[16][132];
    __shared__ float Bs[16][132];

    int wsel = blockIdx.y;
    const float* W = (wsel == 0) ? qw : (wsel == 1) ? kw : vw;
    const float* Bb = (wsel == 0) ? qb : (wsel == 1) ? kb : vb;
    float* C;
    int cs;
    if (wsel == 0)      { C = g_Q;        cs = 128; }
    else if (wsel == 1) { C = g_KV;       cs = 256; }
    else                { C = g_KV + 128; cs = 256; }

    int m0 = blockIdx.x * 128;
    int tid = threadIdx.x;
    int tx = tid & 15, ty = tid >> 4;

    float acc[8][8];
#pragma unroll
    for (int i = 0; i < 8; i++)
#pragma unroll
        for (int j = 0; j < 8; j++) acc[i][j] = 0.0f;

    for (int k0 = 0; k0 < D; k0 += 16) {
#pragma unroll
        for (int f = tid; f < 512; f += 256) {
            int r = f >> 2, kq = (f & 3) * 4;
            int gr = m0 + r;
            float4 v = make_float4(0.f, 0.f, 0.f, 0.f);
            if (gr < N) v = *(const float4*)(X + (size_t)gr * D + k0 + kq);
            As[kq + 0][r] = v.x; As[kq + 1][r] = v.y;
            As[kq + 2][r] = v.z; As[kq + 3][r] = v.w;
        }
#pragma unroll
        for (int f = tid; f < 512; f += 256) {
            int r = f >> 2, kq = (f & 3) * 4;
            float4 v = *(const float4*)(W + (size_t)r * D + k0 + kq);
            Bs[kq + 0][r] = v.x; Bs[kq + 1][r] = v.y;
            Bs[kq + 2][r] = v.z; Bs[kq + 3][r] = v.w;
        }
        __syncthreads();
#pragma unroll
        for (int k = 0; k < 16; k++) {
            float4 a0 = *(const float4*)&As[k][ty * 4];
            float4 a1 = *(const float4*)&As[k][64 + ty * 4];
            float4 b0 = *(const float4*)&Bs[k][tx * 4];
            float4 b1 = *(const float4*)&Bs[k][64 + tx * 4];
            float a[8] = {a0.x, a0.y, a0.z, a0.w, a1.x, a1.y, a1.z, a1.w};
            float b[8] = {b0.x, b0.y, b0.z, b0.w, b1.x, b1.y, b1.z, b1.w};
#pragma unroll
            for (int i = 0; i < 8; i++)
#pragma unroll
                for (int j = 0; j < 8; j++)
                    acc[i][j] += a[i] * b[j];
        }
        __syncthreads();
    }

#pragma unroll
    for (int gi = 0; gi < 2; gi++) {
#pragma unroll
        for (int i = 0; i < 4; i++) {
            int gr = m0 + gi * 64 + ty * 4 + i;
            if (gr >= N) continue;
            int ai = gi * 4 + i;
#pragma unroll
            for (int gj = 0; gj < 2; gj++) {
                int gc = gj * 64 + tx * 4;
                int aj = gj * 4;
                float4 o;
                o.x = acc[ai][aj + 0] + Bb[gc + 0];
                o.y = acc[ai][aj + 1] + Bb[gc + 1];
                o.z = acc[ai][aj + 2] + Bb[gc + 2];
                o.w = acc[ai][aj + 3] + Bb[gc + 3];
                *(float4*)(C + (size_t)gr * cs + gc) = o;
            }
        }
    }
}

// ---------------- fused attention: warp per dst node, online softmax ------
__global__ void k_attn(float* __restrict__ dout, int layer, int N) {
    int gw = (blockIdx.x * blockDim.x + threadIdx.x) >> 5;
    int lane = threadIdx.x & 31;
    if (gw >= N) return;

    float* outp = layer ? dout : g_H;

    int beg = g_start[gw], end = g_start[gw + 1];
    float4 q = ((const float4*)(g_Q + (size_t)gw * D))[lane];

    float m = -CUDART_INF_F, s = 0.0f;
    float4 acc = make_float4(0.f, 0.f, 0.f, 0.f);

    float4 kf, vf;
    if (beg < end) {
        int sp = g_csr_src[beg];
        const float4* kv = (const float4*)(g_KV + (size_t)sp * 256);
        kf = kv[lane];
        vf = kv[32 + lane];
    }

    for (int e = beg; e < end; e++) {
        float4 kc = kf, vc = vf;
        if (e + 1 < end) {                      // prefetch next edge
            int sp = g_csr_src[e + 1];
            const float4* kv = (const float4*)(g_KV + (size_t)sp * 256);
            kf = kv[lane];
            vf = kv[32 + lane];
        }
        float p = kc.x * q.x + kc.y * q.y + kc.z * q.z + kc.w * q.w;
#pragma unroll
        for (int o = 16; o; o >>= 1) p += __shfl_xor_sync(0xFFFFFFFFu, p, o);
        p *= 0.08838834764831845f;              // 1/sqrt(128)

        float mn = fmaxf(m, p);
        float c  = __expf(m - mn);              // exp(-inf)=0 on first edge
        float ep = __expf(p - mn);
        s = s * c + ep;
        acc.x = acc.x * c + ep * vc.x;
        acc.y = acc.y * c + ep * vc.y;
        acc.z = acc.z * c + ep * vc.z;
        acc.w = acc.w * c + ep * vc.w;
        m = mn;
    }

    float inv = (s > 0.0f) ? 1.0f / s : 0.0f;   // deg==0 -> zeros (matches ref)
    float4 o = make_float4(acc.x * inv, acc.y * inv, acc.z * inv, acc.w * inv);
    if (!layer) {                                // ELU fused into layer-1 epilogue
        o.x = (o.x > 0.f) ? o.x : expm1f(o.x);
        o.y = (o.y > 0.f) ? o.y : expm1f(o.y);
        o.z = (o.z > 0.f) ? o.z : expm1f(o.z);
        o.w = (o.w > 0.f) ? o.w : expm1f(o.w);
    }
    ((float4*)(outp + (size_t)gw * D))[lane] = o;
}

// ---------------- launch: fork CSR build alongside GEMM-1 ----------------
extern "C" void kernel_launch(void* const* d_in, const int* in_sizes, int n_in,
                              void* d_out, int out_size) {
    const float* x   = (const float*)d_in[0];
    const void*  ei  = d_in[1];
    const float* q1w = (const float*)d_in[2];  const float* q1b = (const float*)d_in[3];
    const float* k1w = (const float*)d_in[4];  const float* k1b = (const float*)d_in[5];
    const float* v1w = (const float*)d_in[6];  const float* v1b = (const float*)d_in[7];
    const float* q2w = (const float*)d_in[8];  const float* q2b = (const float*)d_in[9];
    const float* k2w = (const float*)d_in[10]; const float* k2b = (const float*)d_in[11];
    const float* v2w = (const float*)d_in[12]; const float* v2b = (const float*)d_in[13];

    int N = in_sizes[0] / D;
    int E = in_sizes[1] / 2;
    float* out = (float*)d_out;

    int eb = (E + 255) / 256;
    int nb = (N + 255) / 256;

    // side stream + events, created fresh per call (few calls; capture-legal;
    // not device-memory allocation). Never destroyed mid-capture.
    cudaStream_t s2;
    cudaEvent_t evFork, evJoin;
    cudaStreamCreateWithFlags(&s2, cudaStreamNonBlocking);
    cudaEventCreateWithFlags(&evFork, cudaEventDisableTiming);
    cudaEventCreateWithFlags(&evJoin, cudaEventDisableTiming);

    // fork: CSR build on s2 (depends only on edge_index)
    cudaEventRecord(evFork, 0);
    cudaStreamWaitEvent(s2, evFork, 0);
    k_init_csr<<<nb, 256, 0, s2>>>((const unsigned*)ei, N);
    k_convert<<<eb, 256, 0, s2>>>(ei, E);
    k_scan<<<1, 1024, 0, s2>>>(N);
    k_scatter<<<eb, 256, 0, s2>>>(E);
    cudaEventRecord(evJoin, s2);

    dim3 ggrid((N + 127) / 128, 3);
    int ab = (N * 32 + 255) / 256;

    // GEMM-1 runs concurrently with the CSR build
    k_gemm_qkv<<<ggrid, 256>>>(x, 0, q1w, q1b, k1w, k1b, v1w, v1b, N);

    // join: attention needs both
    cudaStreamWaitEvent(0, evJoin, 0);
    k_attn<<<ab, 256>>>(out, 0, N);

    // layer 2
    k_gemm_qkv<<<ggrid, 256>>>(x, 1, q2w, q2b, k2w, k2b, v2w, v2b, N);
    k_attn<<<ab, 256>>>(out, 1, N);
}